// round 1
// baseline (speedup 1.0000x reference)
#include <cuda_runtime.h>

// Problem constants
#define BB   2
#define CC   64
#define HH   256
#define WWI  256
#define HWN  (HH*WWI)      // 65536
#define IC1  128
#define OC1  128
#define OC2  576
#define EPSF 1e-5f

// ---------------- scratch (static device globals; no allocations) ----------
__device__ float g_t[BB*OC1*HWN];       // conv1 outputs (relu): ch 0-63 = t1 (cw branch), 64-127 = t2 (dw branch)
__device__ float g_w1t[IC1*9*OC1];      // conv1 weights transposed: [red=ic*9+r*3+s][oc]
__device__ float g_w2t[CC*9*OC2];       // conv2 weights transposed: [red][oc]
__device__ float g_y[BB*CC*HWN];        // guided-conv output
__device__ float g_z[BB*CC*HWN];        // einsum output (pre-BN)
__device__ float g_hmean[BB*CC];
__device__ float g_dwT[BB*CC*CC];       // [b][c][o]
__device__ float g_sum[CC];
__device__ float g_sumsq[CC];

// ---------------- weight transposes ----------------------------------------
__global__ void k_wt1(const float* __restrict__ cw_w1, const float* __restrict__ dw_w1) {
    int idx = blockIdx.x*blockDim.x + threadIdx.x;
    if (idx >= IC1*9*OC1) return;
    int oc  = idx % OC1;
    int red = idx / OC1;           // ic*9 + r*3 + s
    int ic  = red / 9, rs = red % 9;
    const float* w = (oc < 64) ? cw_w1 : dw_w1;
    int o = (oc < 64) ? oc : oc - 64;
    g_w1t[idx] = w[(o*IC1 + ic)*9 + rs];
}

__global__ void k_wt2(const float* __restrict__ cw_w2) {
    int idx = blockIdx.x*blockDim.x + threadIdx.x;
    if (idx >= CC*9*OC2) return;
    int oc  = idx % OC2;
    int red = idx / OC2;
    int ic  = red / 9, rs = red % 9;
    g_w2t[idx] = cw_w2[(oc*CC + ic)*9 + rs];
}

// ---------------- conv1: both KGN first convs fused, 128 oc, relu ----------
// block: 512 thr = 16 warps; warp -> 8 oc; lanes -> 128-px row tile (4 px/lane)
__global__ void k_conv1(const float* __restrict__ input, const float* __restrict__ guidance,
                        const float* __restrict__ cw_b1, const float* __restrict__ dw_b1) {
    extern __shared__ float sm[];
    float* ts = sm;              // [8][3][130] = 3120
    float* ws = sm + 3120;       // [72][128]   = 9216
    int tid = threadIdx.x, lane = tid & 31, warp = tid >> 5;
    int w0 = blockIdx.x * 128;
    int h  = blockIdx.y;
    int b  = blockIdx.z;
    int oc0 = warp * 8;

    float acc[8][4];
    #pragma unroll
    for (int i = 0; i < 8; i++)
        #pragma unroll
        for (int j = 0; j < 4; j++) acc[i][j] = 0.f;

    for (int icc = 0; icc < 16; icc++) {
        int ic0 = icc * 8;
        __syncthreads();
        for (int i = tid; i < 3120; i += 512) {
            int x = i % 130;
            int t = i / 130;
            int r = t % 3;
            int ci = t / 3;
            int hh = h - 1 + r;
            int ww = w0 - 1 + x;
            float v = 0.f;
            if (hh >= 0 && hh < HH && ww >= 0 && ww < WWI) {
                int ic = ic0 + ci;
                const float* src = (ic < 64) ? input : guidance;
                int icl = (ic < 64) ? ic : ic - 64;
                v = src[((b*64 + icl)*HH + hh)*WWI + ww];
            }
            ts[i] = v;
        }
        for (int i = tid; i < 72*128; i += 512)
            ws[i] = g_w1t[ic0*9*128 + i];
        __syncthreads();

        #pragma unroll 2
        for (int ci = 0; ci < 8; ci++) {
            #pragma unroll
            for (int r = 0; r < 3; r++) {
                #pragma unroll
                for (int s = 0; s < 3; s++) {
                    int rr = ci*9 + r*3 + s;
                    const float4* wp = (const float4*)&ws[rr*128 + oc0];
                    float4 wa = wp[0], wb = wp[1];
                    float wv[8] = {wa.x, wa.y, wa.z, wa.w, wb.x, wb.y, wb.z, wb.w};
                    float tv[4];
                    #pragma unroll
                    for (int j = 0; j < 4; j++)
                        tv[j] = ts[(ci*3 + r)*130 + lane + j*32 + s];
                    #pragma unroll
                    for (int i = 0; i < 8; i++)
                        #pragma unroll
                        for (int j = 0; j < 4; j++)
                            acc[i][j] += wv[i]*tv[j];
                }
            }
        }
    }
    #pragma unroll
    for (int i = 0; i < 8; i++) {
        int oc = oc0 + i;
        float bias = (oc < 64) ? cw_b1[oc] : dw_b1[oc - 64];
        #pragma unroll
        for (int j = 0; j < 4; j++) {
            float v = fmaxf(acc[i][j] + bias, 0.f);
            g_t[((b*OC1 + oc)*HH + h)*WWI + w0 + lane + j*32] = v;
        }
    }
}

// ---------------- GAP of dw-branch conv ------------------------------------
__global__ void k_hmean() {
    int b = blockIdx.x >> 6;
    int c = blockIdx.x & 63;
    const float* p = &g_t[(b*OC1 + 64 + c)*HWN];
    float s = 0.f;
    for (int i = threadIdx.x; i < HWN; i += 256) s += p[i];
    __shared__ float red[256];
    red[threadIdx.x] = s; __syncthreads();
    for (int k = 128; k > 0; k >>= 1) {
        if (threadIdx.x < k) red[threadIdx.x] += red[threadIdx.x + k];
        __syncthreads();
    }
    if (threadIdx.x == 0) g_hmean[b*CC + c] = red[0] * (1.f/HWN);
}

// ---------------- depthwise-mixing 1x1 weights -----------------------------
__global__ void k_dw(const float* __restrict__ dw_w2, const float* __restrict__ dw_b2) {
    int idx = blockIdx.x*blockDim.x + threadIdx.x;  // (b*64 + o)*64 + c
    if (idx >= BB*CC*CC) return;
    int c = idx & 63;
    int o = (idx >> 6) & 63;
    int b = idx >> 12;
    float s = dw_b2[o*CC + c];
    const float* wrow = &dw_w2[(o*CC + c)*CC];
    const float* hm = &g_hmean[b*CC];
    #pragma unroll 8
    for (int ic = 0; ic < CC; ic++) s += hm[ic]*wrow[ic];
    g_dwT[(b*CC + c)*CC + o] = s;
}

// ---------------- fused conv2 (64->576) + guided depthwise combine ---------
// block: 512 thr = 16 warps; warp -> 1 c (9 accumulated cw values); 128-px tile
__global__ void k_conv2g(const float* __restrict__ input, const float* __restrict__ cw_b2) {
    extern __shared__ float sm[];
    float* ts = sm;               // [8][3][130] = 3120
    float* ws = sm + 3120;        // [72][16][12] = 13824 (pad 9->12 for float4)
    int tid = threadIdx.x, lane = tid & 31, warp = tid >> 5;
    int w0 = blockIdx.x * 128;
    int h  = blockIdx.y;
    int b  = blockIdx.z >> 2;
    int c0 = (blockIdx.z & 3) * 16;
    int c  = c0 + warp;

    float acc[4][9];
    #pragma unroll
    for (int j = 0; j < 4; j++)
        #pragma unroll
        for (int k = 0; k < 9; k++) acc[j][k] = cw_b2[c*9 + k];

    for (int icc = 0; icc < 8; icc++) {
        int ic0 = icc * 8;
        __syncthreads();
        for (int i = tid; i < 3120; i += 512) {
            int x = i % 130;
            int t = i / 130;
            int r = t % 3;
            int ci = t / 3;
            int hh = h - 1 + r;
            int ww = w0 - 1 + x;
            float v = 0.f;
            if (hh >= 0 && hh < HH && ww >= 0 && ww < WWI)
                v = g_t[((b*OC1 + ic0 + ci)*HH + hh)*WWI + ww];
            ts[i] = v;
        }
        for (int i = tid; i < 72*144; i += 512) {
            int rr = i / 144, rem = i % 144;
            int wv = rem / 9, k = rem % 9;
            ws[(rr*16 + wv)*12 + k] = g_w2t[(ic0*9 + rr)*OC2 + c0*9 + rem];
        }
        __syncthreads();

        #pragma unroll 2
        for (int ci = 0; ci < 8; ci++) {
            #pragma unroll
            for (int r = 0; r < 3; r++) {
                #pragma unroll
                for (int s = 0; s < 3; s++) {
                    int rr = ci*9 + r*3 + s;
                    const float* wp = &ws[(rr*16 + warp)*12];
                    float4 wa = *(const float4*)wp;
                    float4 wb = *(const float4*)(wp + 4);
                    float w8 = wp[8];
                    float tv[4];
                    #pragma unroll
                    for (int j = 0; j < 4; j++)
                        tv[j] = ts[(ci*3 + r)*130 + lane + j*32 + s];
                    #pragma unroll
                    for (int j = 0; j < 4; j++) {
                        acc[j][0] += tv[j]*wa.x;
                        acc[j][1] += tv[j]*wa.y;
                        acc[j][2] += tv[j]*wa.z;
                        acc[j][3] += tv[j]*wa.w;
                        acc[j][4] += tv[j]*wb.x;
                        acc[j][5] += tv[j]*wb.y;
                        acc[j][6] += tv[j]*wb.z;
                        acc[j][7] += tv[j]*wb.w;
                        acc[j][8] += tv[j]*w8;
                    }
                }
            }
        }
    }
    // combine with 3x3 input patches (patch order k = kh*3+kw, cw channel 9c+k)
    #pragma unroll
    for (int j = 0; j < 4; j++) {
        int wpx = w0 + lane + j*32;
        float y = 0.f;
        #pragma unroll
        for (int kh = 0; kh < 3; kh++) {
            int hh = h - 1 + kh;
            #pragma unroll
            for (int kw = 0; kw < 3; kw++) {
                int wwp = wpx - 1 + kw;
                float pv = 0.f;
                if (hh >= 0 && hh < HH && wwp >= 0 && wwp < WWI)
                    pv = input[((b*CC + c)*HH + hh)*WWI + wwp];
                y += acc[j][kh*3 + kw]*pv;
            }
        }
        g_y[((b*CC + c)*HH + h)*WWI + wpx] = y;
    }
}

// ---------------- per-sample 1x1 (einsum) ----------------------------------
__global__ void k_einsum() {
    extern __shared__ float sm[];
    float* sy  = sm;              // [64][256]
    float* sdw = sm + 64*256;     // [c][o] 64x64
    int tid = threadIdx.x;        // 256
    int h = blockIdx.x & 255;
    int b = blockIdx.x >> 8;
    for (int c = 0; c < 64; c++)
        sy[c*256 + tid] = g_y[(b*CC + c)*HWN + h*WWI + tid];
    for (int i = tid; i < 4096; i += 256)
        sdw[i] = g_dwT[b*4096 + i];
    __syncthreads();

    float accz[64];
    #pragma unroll
    for (int o = 0; o < 64; o++) accz[o] = 0.f;
    #pragma unroll 4
    for (int c = 0; c < 64; c++) {
        float yv = sy[c*256 + tid];
        const float4* dp = (const float4*)&sdw[c*64];
        #pragma unroll
        for (int o4 = 0; o4 < 16; o4++) {
            float4 d = dp[o4];
            accz[o4*4+0] += yv*d.x;
            accz[o4*4+1] += yv*d.y;
            accz[o4*4+2] += yv*d.z;
            accz[o4*4+3] += yv*d.w;
        }
    }
    #pragma unroll
    for (int o = 0; o < 64; o++)
        g_z[(b*CC + o)*HWN + h*WWI + tid] = accz[o];
}

// ---------------- BN stats ---------------------------------------------------
__global__ void k_zero() {
    int i = threadIdx.x;
    if (i < CC) { g_sum[i] = 0.f; g_sumsq[i] = 0.f; }
}

__global__ void k_stats() {
    int o = blockIdx.x >> 2, part = blockIdx.x & 3;  // 4 blocks per channel
    float s = 0.f, s2 = 0.f;
    for (int b = 0; b < BB; b++) {
        const float* p = &g_z[(b*CC + o)*HWN + part*16384];
        for (int i = threadIdx.x; i < 16384; i += 256) {
            float v = p[i]; s += v; s2 += v*v;
        }
    }
    __shared__ float r1[256], r2[256];
    r1[threadIdx.x] = s; r2[threadIdx.x] = s2; __syncthreads();
    for (int k = 128; k > 0; k >>= 1) {
        if (threadIdx.x < k) { r1[threadIdx.x] += r1[threadIdx.x + k]; r2[threadIdx.x] += r2[threadIdx.x + k]; }
        __syncthreads();
    }
    if (threadIdx.x == 0) { atomicAdd(&g_sum[o], r1[0]); atomicAdd(&g_sumsq[o], r2[0]); }
}

// ---------------- BN normalize + relu ---------------------------------------
__global__ void k_bn(const float* __restrict__ gamma, const float* __restrict__ beta,
                     float* __restrict__ out) {
    const float invN = 1.f/(float)(BB*HWN);
    int idx = blockIdx.x*blockDim.x + threadIdx.x;
    int stride = gridDim.x*blockDim.x;
    int total4 = BB*CC*HWN/4;
    const float4* zp = (const float4*)g_z;
    float4* op = (float4*)out;
    for (int i = idx; i < total4; i += stride) {
        int o = (i >> 14) & 63;
        float mu  = g_sum[o]*invN;
        float var = g_sumsq[o]*invN - mu*mu;
        float rs  = rsqrtf(var + EPSF);
        float ga = gamma[o]*rs, be = beta[o];
        float4 z = zp[i];
        float4 r;
        r.x = fmaxf((z.x - mu)*ga + be, 0.f);
        r.y = fmaxf((z.y - mu)*ga + be, 0.f);
        r.z = fmaxf((z.z - mu)*ga + be, 0.f);
        r.w = fmaxf((z.w - mu)*ga + be, 0.f);
        op[i] = r;
    }
}

// ---------------- launch -----------------------------------------------------
extern "C" void kernel_launch(void* const* d_in, const int* in_sizes, int n_in,
                              void* d_out, int out_size) {
    const float* input    = (const float*)d_in[0];
    const float* guidance = (const float*)d_in[1];
    const float* cw_w1    = (const float*)d_in[2];
    const float* cw_b1    = (const float*)d_in[3];
    const float* cw_w2    = (const float*)d_in[4];
    const float* cw_b2    = (const float*)d_in[5];
    const float* dw_w1    = (const float*)d_in[6];
    const float* dw_b1    = (const float*)d_in[7];
    const float* dw_w2    = (const float*)d_in[8];
    const float* dw_b2    = (const float*)d_in[9];
    const float* bn_gamma = (const float*)d_in[10];
    const float* bn_beta  = (const float*)d_in[11];
    float* out = (float*)d_out;

    cudaFuncSetAttribute(k_conv1,  cudaFuncAttributeMaxDynamicSharedMemorySize, (3120 + 72*128)*4);
    cudaFuncSetAttribute(k_conv2g, cudaFuncAttributeMaxDynamicSharedMemorySize, (3120 + 72*16*12)*4);
    cudaFuncSetAttribute(k_einsum, cudaFuncAttributeMaxDynamicSharedMemorySize, (64*256 + 64*64)*4);

    k_wt1<<<(IC1*9*OC1 + 255)/256, 256>>>(cw_w1, dw_w1);
    k_wt2<<<(CC*9*OC2 + 255)/256, 256>>>(cw_w2);
    k_conv1<<<dim3(2, 256, 2), 512, (3120 + 72*128)*4>>>(input, guidance, cw_b1, dw_b1);
    k_hmean<<<128, 256>>>();
    k_dw<<<(BB*CC*CC + 255)/256, 256>>>(dw_w2, dw_b2);
    k_conv2g<<<dim3(2, 256, 8), 512, (3120 + 72*16*12)*4>>>(input, cw_b2);
    k_einsum<<<512, 256, (64*256 + 64*64)*4>>>();
    k_zero<<<1, 64>>>();
    k_stats<<<256, 256>>>();
    k_bn<<<1024, 256>>>(bn_gamma, bn_beta, out);
}